// round 1
// baseline (speedup 1.0000x reference)
#include <cuda_runtime.h>
#include <math.h>

#define BB 4
#define TT 2048
#define CC 1024
#define HH 16
#define DD 64
#define FF 4096
#define MROWS (BB*TT)   // 8192

// ---------------- scratch (static device globals; no allocation) -------------
__device__ float g_xn[MROWS*CC];
__device__ float g_q[MROWS*CC];
__device__ float g_k[MROWS*CC];
__device__ float g_v[MROWS*CC];     // reused as attn-proj output after scan
__device__ float g_gate[MROWS*CC];  // gate_raw, then sigmoid(gate)*o
__device__ float g_o[MROWS*CC];
__device__ float g_x1[MROWS*CC];
__device__ float g_beta[MROWS*HH];
__device__ float g_gg[MROWS*FF];
__device__ float g_uu[MROWS*FF];

// ---------------- rmsnorm ----------------------------------------------------
__global__ void rmsnorm_k(const float* __restrict__ x, const float* __restrict__ w,
                          float* __restrict__ y) {
    int row = blockIdx.x;
    const float* xr = x + (size_t)row * CC;
    float* yr = y + (size_t)row * CC;
    float v[4];
    float ss = 0.f;
#pragma unroll
    for (int i = 0; i < 4; i++) {
        v[i] = xr[threadIdx.x + i * 256];
        ss += v[i] * v[i];
    }
#pragma unroll
    for (int off = 16; off; off >>= 1) ss += __shfl_xor_sync(0xffffffffu, ss, off);
    __shared__ float sred[8];
    __shared__ float stot;
    if ((threadIdx.x & 31) == 0) sred[threadIdx.x >> 5] = ss;
    __syncthreads();
    if (threadIdx.x < 8) {
        float t = sred[threadIdx.x];
#pragma unroll
        for (int off = 4; off; off >>= 1) t += __shfl_xor_sync(0xffu, t, off);
        if (threadIdx.x == 0) stot = t;
    }
    __syncthreads();
    float r = rsqrtf(stot / (float)CC + 1e-6f);
#pragma unroll
    for (int i = 0; i < 4; i++)
        yr[threadIdx.x + i * 256] = v[i] * r * w[threadIdx.x + i * 256];
}

// ---------------- SGEMM: C[M,N] = A[M,K] * B[N,K]^T --------------------------
// 128x128 block tile, K-tile 8, 256 threads, 8x8 per thread.
// M assumed divisible by 128; N guarded (for N=16 beta case).
__global__ __launch_bounds__(256)
void sgemm_nt(const float* __restrict__ A, const float* __restrict__ B,
              float* __restrict__ C, int M, int N, int K) {
    __shared__ float As[8][128];
    __shared__ float Bs[8][128];
    const int tid = threadIdx.x;
    const int bm = blockIdx.y * 128;
    const int bn = blockIdx.x * 128;
    const int lrow = tid >> 1;
    const int lcol = (tid & 1) << 2;
    const int tx = tid & 15;
    const int ty = tid >> 4;

    const float* Aptr = A + (size_t)(bm + lrow) * K + lcol;
    const float* Bptr = B + (size_t)(bn + lrow) * K + lcol;
    const bool bvalid = (bn + lrow) < N;

    float acc[8][8];
#pragma unroll
    for (int i = 0; i < 8; i++)
#pragma unroll
        for (int j = 0; j < 8; j++) acc[i][j] = 0.f;

    for (int k0 = 0; k0 < K; k0 += 8) {
        float4 av = *(const float4*)(Aptr + k0);
        float4 bv = bvalid ? *(const float4*)(Bptr + k0) : make_float4(0.f, 0.f, 0.f, 0.f);
        As[lcol + 0][lrow] = av.x; As[lcol + 1][lrow] = av.y;
        As[lcol + 2][lrow] = av.z; As[lcol + 3][lrow] = av.w;
        Bs[lcol + 0][lrow] = bv.x; Bs[lcol + 1][lrow] = bv.y;
        Bs[lcol + 2][lrow] = bv.z; Bs[lcol + 3][lrow] = bv.w;
        __syncthreads();
#pragma unroll
        for (int kk = 0; kk < 8; kk++) {
            float ar[8], br[8];
            *(float4*)(ar)     = *(const float4*)&As[kk][ty * 8];
            *(float4*)(ar + 4) = *(const float4*)&As[kk][ty * 8 + 4];
            *(float4*)(br)     = *(const float4*)&Bs[kk][tx * 8];
            *(float4*)(br + 4) = *(const float4*)&Bs[kk][tx * 8 + 4];
#pragma unroll
            for (int i = 0; i < 8; i++)
#pragma unroll
                for (int j = 0; j < 8; j++)
                    acc[i][j] += ar[i] * br[j];
        }
        __syncthreads();
    }
#pragma unroll
    for (int i = 0; i < 8; i++) {
        int row = bm + ty * 8 + i;
#pragma unroll
        for (int j = 0; j < 8; j++) {
            int col = bn + tx * 8 + j;
            if (col < N) C[(size_t)row * N + col] = acc[i][j];
        }
    }
}

// ---------------- elementwise helpers ----------------------------------------
__global__ void beta_post_k(float* __restrict__ b, const float* __restrict__ bias) {
    int i = blockIdx.x * 256 + threadIdx.x;
    if (i < MROWS * HH) {
        float t = b[i] + bias[i & (HH - 1)];
        b[i] = 1.f / (1.f + __expf(-t));
    }
}

__global__ void l2norm_k(float* __restrict__ x) {
    // one warp per 64-vector, 8 warps/block
    int vec = blockIdx.x * 8 + (threadIdx.x >> 5);
    int lane = threadIdx.x & 31;
    float* p = x + (size_t)vec * 64;
    float a = p[lane], b = p[lane + 32];
    float ss = a * a + b * b;
#pragma unroll
    for (int off = 16; off; off >>= 1) ss += __shfl_xor_sync(0xffffffffu, ss, off);
    float inv = 1.f / fmaxf(sqrtf(ss), 1e-12f);
    p[lane] = a * inv;
    p[lane + 32] = b * inv;
}

__global__ void gate_mul_k(float* __restrict__ gate, const float* __restrict__ o) {
    int i = blockIdx.x * 256 + threadIdx.x;
    float gr = gate[i];
    gate[i] = o[i] / (1.f + __expf(-gr));
}

__global__ void resadd_k(const float* __restrict__ a, const float* __restrict__ b,
                         float* __restrict__ y) {
    int i = blockIdx.x * 256 + threadIdx.x;
    y[i] = a[i] + b[i];
}

__global__ void silu_mul_k(float* __restrict__ g, const float* __restrict__ u) {
    int i = blockIdx.x * 256 + threadIdx.x;
    float gv = g[i];
    g[i] = (gv / (1.f + __expf(-gv))) * u[i];
}

__global__ void final_add_k(float* __restrict__ out, const float* __restrict__ x1) {
    int i = blockIdx.x * 256 + threadIdx.x;
    out[i] += x1[i];
}

// ---------------- delta-rule scan --------------------------------------------
// grid = B*H blocks, 128 threads. tid = 2*d + s; thread owns M[d][32s .. 32s+31]
// in registers. q/k staged through double-buffered shared; v/beta per-thread.
// Global loads for t+1 prefetched during compute of t.
__global__ __launch_bounds__(128)
void delta_scan_k(const float* __restrict__ q, const float* __restrict__ k,
                  const float* __restrict__ v, const float* __restrict__ beta,
                  float* __restrict__ o) {
    const int b = blockIdx.x / HH;
    const int h = blockIdx.x % HH;
    const int tid = threadIdx.x;
    const int d = tid >> 1;
    const int s = tid & 1;
    const int cbase = s * 32;

    __shared__ float qs[2][64];
    __shared__ float ks[2][64];

    float Mrow[32];
#pragma unroll
    for (int j = 0; j < 32; j++) Mrow[j] = 0.f;

    const float* qb = q + (size_t)b * TT * CC + h * DD;
    const float* kb = k + (size_t)b * TT * CC + h * DD;
    const float* vb = v + (size_t)b * TT * CC + h * DD;
    const float* bb = beta + (size_t)b * TT * HH + h;
    float* ob = o + (size_t)b * TT * CC + h * DD;

    // prefetch t = 0
    float rqk = (tid < 64) ? qb[tid] : kb[tid - 64];
    float rv = vb[d];
    float rb = bb[0];

    int buf = 0;
    for (int t = 0; t < TT; t++) {
        if (tid < 64) qs[buf][tid] = rqk; else ks[buf][tid - 64] = rqk;
        __syncthreads();
        float cv = rv, cb = rb;
        if (t + 1 < TT) {
            const int off = (t + 1) * CC;
            rqk = (tid < 64) ? qb[off + tid] : kb[off + tid - 64];
            rv = vb[off + d];
            rb = bb[(t + 1) * HH];
        }
        float po0 = 0.f, po1 = 0.f, pm0 = 0.f, pm1 = 0.f;
#pragma unroll
        for (int j = 0; j < 32; j += 2) {
            float q0 = qs[buf][cbase + j], q1 = qs[buf][cbase + j + 1];
            float k0 = ks[buf][cbase + j], k1 = ks[buf][cbase + j + 1];
            po0 += Mrow[j] * q0;
            po1 += Mrow[j + 1] * q1;
            pm0 += Mrow[j] * k0;
            pm1 += Mrow[j + 1] * k1;
        }
        float po = po0 + po1, pm = pm0 + pm1;
        po += __shfl_xor_sync(0xffffffffu, po, 1);
        pm += __shfl_xor_sync(0xffffffffu, pm, 1);
        float dvb = cb * (cv - pm);
#pragma unroll
        for (int j = 0; j < 32; j++) Mrow[j] += dvb * ks[buf][cbase + j];
        if (s == 0) ob[(size_t)t * CC + d] = po;
        buf ^= 1;
    }
}

// ---------------- launch ------------------------------------------------------
extern "C" void kernel_launch(void* const* d_in, const int* in_sizes, int n_in,
                              void* d_out, int out_size) {
    const float* x       = (const float*)d_in[0];
    // d_in[1] cos, d_in[2] sin : unused (layer_idx=0 branch)
    const float* norm1_w = (const float*)d_in[3];
    const float* norm2_w = (const float*)d_in[4];
    const float* q_w     = (const float*)d_in[5];
    const float* k_w     = (const float*)d_in[6];
    const float* v_w     = (const float*)d_in[7];
    const float* beta_w  = (const float*)d_in[8];
    const float* beta_b  = (const float*)d_in[9];
    const float* gate_w  = (const float*)d_in[10];
    const float* o_w     = (const float*)d_in[11];
    const float* fg_w    = (const float*)d_in[12];
    const float* fu_w    = (const float*)d_in[13];
    const float* fd_w    = (const float*)d_in[14];
    float* out = (float*)d_out;

    float *xn, *q, *k, *v, *gate, *o, *x1, *beta, *gg, *uu;
    cudaGetSymbolAddress((void**)&xn,   g_xn);
    cudaGetSymbolAddress((void**)&q,    g_q);
    cudaGetSymbolAddress((void**)&k,    g_k);
    cudaGetSymbolAddress((void**)&v,    g_v);
    cudaGetSymbolAddress((void**)&gate, g_gate);
    cudaGetSymbolAddress((void**)&o,    g_o);
    cudaGetSymbolAddress((void**)&x1,   g_x1);
    cudaGetSymbolAddress((void**)&beta, g_beta);
    cudaGetSymbolAddress((void**)&gg,   g_gg);
    cudaGetSymbolAddress((void**)&uu,   g_uu);

    const int EW = MROWS * CC / 256;  // elementwise grid for C-wide tensors

    // ---- attention branch ----
    rmsnorm_k<<<MROWS, 256>>>(x, norm1_w, xn);
    sgemm_nt<<<dim3(CC / 128, MROWS / 128), 256>>>(xn, q_w,    q,    MROWS, CC, CC);
    sgemm_nt<<<dim3(CC / 128, MROWS / 128), 256>>>(xn, k_w,    k,    MROWS, CC, CC);
    sgemm_nt<<<dim3(CC / 128, MROWS / 128), 256>>>(xn, v_w,    v,    MROWS, CC, CC);
    sgemm_nt<<<dim3(CC / 128, MROWS / 128), 256>>>(xn, gate_w, gate, MROWS, CC, CC);
    sgemm_nt<<<dim3(1,        MROWS / 128), 256>>>(xn, beta_w, beta, MROWS, HH, CC);
    beta_post_k<<<(MROWS * HH) / 256, 256>>>(beta, beta_b);
    l2norm_k<<<(MROWS * HH) / 8, 256>>>(q);
    l2norm_k<<<(MROWS * HH) / 8, 256>>>(k);
    delta_scan_k<<<BB * HH, 128>>>(q, k, v, beta, o);
    gate_mul_k<<<EW, 256>>>(gate, o);                      // gate <- sigmoid(gate)*o
    sgemm_nt<<<dim3(CC / 128, MROWS / 128), 256>>>(gate, o_w, v, MROWS, CC, CC);  // v <- attn out
    resadd_k<<<EW, 256>>>(x, v, x1);

    // ---- FFN branch ----
    rmsnorm_k<<<MROWS, 256>>>(x1, norm2_w, xn);
    sgemm_nt<<<dim3(FF / 128, MROWS / 128), 256>>>(xn, fg_w, gg, MROWS, FF, CC);
    sgemm_nt<<<dim3(FF / 128, MROWS / 128), 256>>>(xn, fu_w, uu, MROWS, FF, CC);
    silu_mul_k<<<(MROWS * FF) / 256, 256>>>(gg, uu);       // gg <- silu(gg)*uu
    sgemm_nt<<<dim3(CC / 128, MROWS / 128), 256>>>(gg, fd_w, out, MROWS, CC, FF);
    final_add_k<<<EW, 256>>>(out, x1);
}

// round 4
// speedup vs baseline: 2.5134x; 2.5134x over previous
#include <cuda_runtime.h>
#include <cuda_bf16.h>
#include <cstdint>
#include <math.h>

#define BB 4
#define TT 2048
#define CC 1024
#define HH 16
#define DD 64
#define FF 4096
#define MROWS (BB*TT)   // 8192

// ---------------- scratch (static device globals; no allocation) -------------
__device__ float g_xn[MROWS*CC];
__device__ float g_q[MROWS*CC];
__device__ float g_k[MROWS*CC];
__device__ float g_v[MROWS*CC];     // reused as attn-proj output
__device__ float g_gate[MROWS*CC];
__device__ float g_o[MROWS*CC];
__device__ float g_x1[MROWS*CC];
__device__ float g_beta[MROWS*HH];
__device__ float g_gg[MROWS*FF];
__device__ float g_uu[MROWS*FF];
// bf16 split buffers
__device__ __align__(16) __nv_bfloat16 g_a_hi[MROWS*FF];
__device__ __align__(16) __nv_bfloat16 g_a_lo[MROWS*FF];
__device__ __align__(16) __nv_bfloat16 g_w_hi[FF*CC];
__device__ __align__(16) __nv_bfloat16 g_w_lo[FF*CC];

// ================= PTX helpers (plain sm_103-safe: sm_80-era ops only) =======
__device__ __forceinline__ uint32_t smem_u32(const void* p) {
    return (uint32_t)__cvta_generic_to_shared(p);
}
__device__ __forceinline__ void cp16(uint32_t dst, const void* src) {
    asm volatile("cp.async.cg.shared.global [%0], [%1], 16;\n" :: "r"(dst), "l"(src));
}
__device__ __forceinline__ void cp_commit() {
    asm volatile("cp.async.commit_group;\n" ::: "memory");
}
__device__ __forceinline__ void ldsm4(uint32_t* d, uint32_t addr) {
    asm volatile("ldmatrix.sync.aligned.m8n8.x4.shared.b16 {%0,%1,%2,%3}, [%4];"
                 : "=r"(d[0]), "=r"(d[1]), "=r"(d[2]), "=r"(d[3]) : "r"(addr));
}
__device__ __forceinline__ void mma_bf16(float* c, const uint32_t* a,
                                         uint32_t b0, uint32_t b1) {
    asm volatile(
        "mma.sync.aligned.m16n8k16.row.col.f32.bf16.bf16.f32 "
        "{%0,%1,%2,%3}, {%4,%5,%6,%7}, {%8,%9}, {%0,%1,%2,%3};"
        : "+f"(c[0]), "+f"(c[1]), "+f"(c[2]), "+f"(c[3])
        : "r"(a[0]), "r"(a[1]), "r"(a[2]), "r"(a[3]), "r"(b0), "r"(b1));
}

// ================= split-bf16 GEMM via mma.sync ==============================
// C[M,N] = (Ah+Al)[M,K] * (Bh+Bl)[N,K]^T (fp32), via hh + hl + lh.
// CTA 128x128, 8 warps (warp tile 32x64), K staged 64, SW128 swizzle, 2 stages.
#define TILE_MN 128
#define KT 64
#define SUB_BYTES (128*128)         // one 128-row x 128B subtile = 16KB
#define OFF_A_HI 0
#define OFF_A_LO (SUB_BYTES)
#define OFF_B_HI (2*SUB_BYTES)
#define OFF_B_LO (3*SUB_BYTES)
#define STAGE_BYTES (4*SUB_BYTES)   // 64KB
#define GSMEM_TOTAL (2*STAGE_BYTES) // 128KB

__device__ __forceinline__ void load_tile(const __nv_bfloat16* __restrict__ g, int ldk,
                                          int row0, int k0, uint32_t dstbase, int tid) {
    // 128 rows x 128B (64 bf16), SW128 swizzle
#pragma unroll
    for (int i = tid; i < 128 * 8; i += 256) {
        int r = i >> 3;
        int c16 = i & 7;
        const __nv_bfloat16* src = g + (size_t)(row0 + r) * ldk + k0 + c16 * 8;
        uint32_t dst = dstbase + r * 128 + (((uint32_t)(c16 ^ (r & 7))) << 4);
        cp16(dst, src);
    }
}

__global__ __launch_bounds__(256, 1)
void gemm_mma(float* __restrict__ C,
              const __nv_bfloat16* __restrict__ Ah, const __nv_bfloat16* __restrict__ Al,
              const __nv_bfloat16* __restrict__ Bh, const __nv_bfloat16* __restrict__ Bl,
              int M, int N, int K) {
    extern __shared__ __align__(1024) char smem[];
    const uint32_t sbase = smem_u32(smem);
    const int tid = threadIdx.x;
    const int wid = tid >> 5;
    const int lane = tid & 31;
    const int wm = wid & 3;          // 4 m-groups of 32 rows
    const int wn = wid >> 2;         // 2 n-groups of 64 cols
    const int bm = blockIdx.y * TILE_MN;
    const int bn = blockIdx.x * TILE_MN;

    // ldmatrix per-lane addressing constants
    const int mi = lane >> 3;        // matrix index 0..3
    const int lr = lane & 7;         // row within matrix
    // A: matrices {m0-7 k0, m8-15 k0, m0-7 k8, m8-15 k8}
    const uint32_t a_off = (uint32_t)(wm * 32 + ((mi & 1) << 3) + lr) * 128;
    const uint32_t a_cb = (uint32_t)(mi >> 1);
    // B: matrices {n0-7 k0, n0-7 k8, n8-15 k0, n8-15 k8}
    const uint32_t b_off = (uint32_t)(wn * 64 + ((mi >> 1) << 3) + lr) * 128;
    const uint32_t b_cb = (uint32_t)(mi & 1);

    float acc[2][8][4];
#pragma unroll
    for (int a = 0; a < 2; a++)
#pragma unroll
        for (int b = 0; b < 8; b++)
#pragma unroll
            for (int c = 0; c < 4; c++) acc[a][b][c] = 0.f;

    const int NC = K / KT;

    // prefetch chunks 0 and 1
    load_tile(Ah, K, bm, 0, sbase + OFF_A_HI, tid);
    load_tile(Al, K, bm, 0, sbase + OFF_A_LO, tid);
    load_tile(Bh, K, bn, 0, sbase + OFF_B_HI, tid);
    load_tile(Bl, K, bn, 0, sbase + OFF_B_LO, tid);
    cp_commit();
    load_tile(Ah, K, bm, KT, sbase + STAGE_BYTES + OFF_A_HI, tid);
    load_tile(Al, K, bm, KT, sbase + STAGE_BYTES + OFF_A_LO, tid);
    load_tile(Bh, K, bn, KT, sbase + STAGE_BYTES + OFF_B_HI, tid);
    load_tile(Bl, K, bn, KT, sbase + STAGE_BYTES + OFF_B_LO, tid);
    cp_commit();

    for (int kc = 0; kc < NC; kc++) {
        const uint32_t sb = sbase + (uint32_t)(kc & 1) * STAGE_BYTES;
        if (kc + 2 < NC) {
            asm volatile("cp.async.wait_group 1;\n" ::: "memory");
        } else {
            asm volatile("cp.async.wait_group 0;\n" ::: "memory");
        }
        __syncthreads();

#pragma unroll
        for (int ki = 0; ki < 4; ki++) {
            uint32_t ah[2][4], al[2][4], bh[4][4], bl[4][4];
            const uint32_t ax = ((uint32_t)(ki * 2) + a_cb) ^ (uint32_t)lr;
            const uint32_t bx = ((uint32_t)(ki * 2) + b_cb) ^ (uint32_t)lr;
#pragma unroll
            for (int mt = 0; mt < 2; mt++) {
                uint32_t aaddr = sb + a_off + (uint32_t)(mt * 2048) + (ax << 4);
                ldsm4(ah[mt], aaddr + OFF_A_HI);
                ldsm4(al[mt], aaddr + OFF_A_LO);
            }
#pragma unroll
            for (int nt = 0; nt < 4; nt++) {
                uint32_t baddr = sb + b_off + (uint32_t)(nt * 2048) + (bx << 4);
                ldsm4(bh[nt], baddr + OFF_B_HI);
                ldsm4(bl[nt], baddr + OFF_B_LO);
            }
#pragma unroll
            for (int mt = 0; mt < 2; mt++)
#pragma unroll
                for (int nt = 0; nt < 4; nt++)
#pragma unroll
                    for (int h = 0; h < 2; h++) {
                        float* c = acc[mt][nt * 2 + h];
                        mma_bf16(c, ah[mt], bh[nt][2 * h], bh[nt][2 * h + 1]); // hh
                        mma_bf16(c, ah[mt], bl[nt][2 * h], bl[nt][2 * h + 1]); // hl
                        mma_bf16(c, al[mt], bh[nt][2 * h], bh[nt][2 * h + 1]); // lh
                    }
        }
        __syncthreads();
        if (kc + 2 < NC) {
            const uint32_t pb = sbase + (uint32_t)(kc & 1) * STAGE_BYTES;
            const int k0 = (kc + 2) * KT;
            load_tile(Ah, K, bm, k0, pb + OFF_A_HI, tid);
            load_tile(Al, K, bm, k0, pb + OFF_A_LO, tid);
            load_tile(Bh, K, bn, k0, pb + OFF_B_HI, tid);
            load_tile(Bl, K, bn, k0, pb + OFF_B_LO, tid);
            cp_commit();
        }
    }

    // epilogue: lane g = lane>>2 (row), t = lane&3 (col pair)
    const int g = lane >> 2;
    const int t = lane & 3;
#pragma unroll
    for (int mt = 0; mt < 2; mt++) {
        const int row0 = bm + wm * 32 + mt * 16 + g;
#pragma unroll
        for (int n8 = 0; n8 < 8; n8++) {
            const int col = bn + wn * 64 + n8 * 8 + t * 2;
            float* c = acc[mt][n8];
            *(float2*)(C + (size_t)row0 * N + col)       = make_float2(c[0], c[1]);
            *(float2*)(C + (size_t)(row0 + 8) * N + col) = make_float2(c[2], c[3]);
        }
    }
}

// ---------------- fp32 -> (hi, lo) bf16 split conversion ---------------------
__global__ void cvt_split_k(const float* __restrict__ x, __nv_bfloat16* __restrict__ hi,
                            __nv_bfloat16* __restrict__ lo, int n4) {
    int i = blockIdx.x * 256 + threadIdx.x;
    if (i >= n4) return;
    float4 v = ((const float4*)x)[i];
    __nv_bfloat16 h0 = __float2bfloat16(v.x);
    __nv_bfloat16 h1 = __float2bfloat16(v.y);
    __nv_bfloat16 h2 = __float2bfloat16(v.z);
    __nv_bfloat16 h3 = __float2bfloat16(v.w);
    __nv_bfloat16 l0 = __float2bfloat16(v.x - __bfloat162float(h0));
    __nv_bfloat16 l1 = __float2bfloat16(v.y - __bfloat162float(h1));
    __nv_bfloat16 l2 = __float2bfloat16(v.z - __bfloat162float(h2));
    __nv_bfloat16 l3 = __float2bfloat16(v.w - __bfloat162float(h3));
    ((__nv_bfloat162*)hi)[2 * i]     = __nv_bfloat162(h0, h1);
    ((__nv_bfloat162*)hi)[2 * i + 1] = __nv_bfloat162(h2, h3);
    ((__nv_bfloat162*)lo)[2 * i]     = __nv_bfloat162(l0, l1);
    ((__nv_bfloat162*)lo)[2 * i + 1] = __nv_bfloat162(l2, l3);
}

// ---------------- rmsnorm ----------------------------------------------------
__global__ void rmsnorm_k(const float* __restrict__ x, const float* __restrict__ w,
                          float* __restrict__ y) {
    int row = blockIdx.x;
    const float* xr = x + (size_t)row * CC;
    float* yr = y + (size_t)row * CC;
    float v[4];
    float ss = 0.f;
#pragma unroll
    for (int i = 0; i < 4; i++) {
        v[i] = xr[threadIdx.x + i * 256];
        ss += v[i] * v[i];
    }
#pragma unroll
    for (int off = 16; off; off >>= 1) ss += __shfl_xor_sync(0xffffffffu, ss, off);
    __shared__ float sred[8];
    __shared__ float stot;
    if ((threadIdx.x & 31) == 0) sred[threadIdx.x >> 5] = ss;
    __syncthreads();
    if (threadIdx.x < 8) {
        float t = sred[threadIdx.x];
#pragma unroll
        for (int off = 4; off; off >>= 1) t += __shfl_xor_sync(0xffu, t, off);
        if (threadIdx.x == 0) stot = t;
    }
    __syncthreads();
    float r = rsqrtf(stot / (float)CC + 1e-6f);
#pragma unroll
    for (int i = 0; i < 4; i++)
        yr[threadIdx.x + i * 256] = v[i] * r * w[threadIdx.x + i * 256];
}

// ---------------- small FFMA GEMM (beta only, N=16) --------------------------
__global__ __launch_bounds__(256)
void sgemm_nt(const float* __restrict__ A, const float* __restrict__ B,
              float* __restrict__ C, int M, int N, int K) {
    __shared__ float As[8][128];
    __shared__ float Bs[8][128];
    const int tid = threadIdx.x;
    const int bm = blockIdx.y * 128;
    const int bn = blockIdx.x * 128;
    const int lrow = tid >> 1;
    const int lcol = (tid & 1) << 2;
    const int tx = tid & 15;
    const int ty = tid >> 4;

    const float* Aptr = A + (size_t)(bm + lrow) * K + lcol;
    const float* Bptr = B + (size_t)(bn + lrow) * K + lcol;
    const bool bvalid = (bn + lrow) < N;

    float acc[8][8];
#pragma unroll
    for (int i = 0; i < 8; i++)
#pragma unroll
        for (int j = 0; j < 8; j++) acc[i][j] = 0.f;

    for (int k0 = 0; k0 < K; k0 += 8) {
        float4 av = *(const float4*)(Aptr + k0);
        float4 bv = bvalid ? *(const float4*)(Bptr + k0) : make_float4(0.f, 0.f, 0.f, 0.f);
        As[lcol + 0][lrow] = av.x; As[lcol + 1][lrow] = av.y;
        As[lcol + 2][lrow] = av.z; As[lcol + 3][lrow] = av.w;
        Bs[lcol + 0][lrow] = bv.x; Bs[lcol + 1][lrow] = bv.y;
        Bs[lcol + 2][lrow] = bv.z; Bs[lcol + 3][lrow] = bv.w;
        __syncthreads();
#pragma unroll
        for (int kk = 0; kk < 8; kk++) {
            float ar[8], br[8];
            *(float4*)(ar)     = *(const float4*)&As[kk][ty * 8];
            *(float4*)(ar + 4) = *(const float4*)&As[kk][ty * 8 + 4];
            *(float4*)(br)     = *(const float4*)&Bs[kk][tx * 8];
            *(float4*)(br + 4) = *(const float4*)&Bs[kk][tx * 8 + 4];
#pragma unroll
            for (int i = 0; i < 8; i++)
#pragma unroll
                for (int j = 0; j < 8; j++)
                    acc[i][j] += ar[i] * br[j];
        }
        __syncthreads();
    }
#pragma unroll
    for (int i = 0; i < 8; i++) {
        int row = bm + ty * 8 + i;
#pragma unroll
        for (int j = 0; j < 8; j++) {
            int col = bn + tx * 8 + j;
            if (col < N) C[(size_t)row * N + col] = acc[i][j];
        }
    }
}

// ---------------- elementwise helpers ----------------------------------------
__global__ void beta_post_k(float* __restrict__ b, const float* __restrict__ bias) {
    int i = blockIdx.x * 256 + threadIdx.x;
    if (i < MROWS * HH) {
        float t = b[i] + bias[i & (HH - 1)];
        b[i] = 1.f / (1.f + __expf(-t));
    }
}

__global__ void l2norm_k(float* __restrict__ x) {
    int vec = blockIdx.x * 8 + (threadIdx.x >> 5);
    int lane = threadIdx.x & 31;
    float* p = x + (size_t)vec * 64;
    float a = p[lane], b = p[lane + 32];
    float ss = a * a + b * b;
#pragma unroll
    for (int off = 16; off; off >>= 1) ss += __shfl_xor_sync(0xffffffffu, ss, off);
    float inv = 1.f / fmaxf(sqrtf(ss), 1e-12f);
    p[lane] = a * inv;
    p[lane + 32] = b * inv;
}

__global__ void gate_mul_k(float* __restrict__ gate, const float* __restrict__ o) {
    int i = blockIdx.x * 256 + threadIdx.x;
    float gr = gate[i];
    gate[i] = o[i] / (1.f + __expf(-gr));
}

__global__ void resadd_k(const float* __restrict__ a, const float* __restrict__ b,
                         float* __restrict__ y) {
    int i = blockIdx.x * 256 + threadIdx.x;
    y[i] = a[i] + b[i];
}

__global__ void silu_mul_k(float* __restrict__ g, const float* __restrict__ u) {
    int i = blockIdx.x * 256 + threadIdx.x;
    float gv = g[i];
    g[i] = (gv / (1.f + __expf(-gv))) * u[i];
}

__global__ void final_add_k(float* __restrict__ out, const float* __restrict__ x1) {
    int i = blockIdx.x * 256 + threadIdx.x;
    out[i] += x1[i];
}

// ---------------- delta-rule scan --------------------------------------------
__global__ __launch_bounds__(128)
void delta_scan_k(const float* __restrict__ q, const float* __restrict__ k,
                  const float* __restrict__ v, const float* __restrict__ beta,
                  float* __restrict__ o) {
    const int b = blockIdx.x / HH;
    const int h = blockIdx.x % HH;
    const int tid = threadIdx.x;
    const int d = tid >> 1;
    const int s = tid & 1;
    const int cbase = s * 32;

    __shared__ float qs[2][64];
    __shared__ float ks[2][64];

    float Mrow[32];
#pragma unroll
    for (int j = 0; j < 32; j++) Mrow[j] = 0.f;

    const float* qb = q + (size_t)b * TT * CC + h * DD;
    const float* kb = k + (size_t)b * TT * CC + h * DD;
    const float* vb = v + (size_t)b * TT * CC + h * DD;
    const float* bb = beta + (size_t)b * TT * HH + h;
    float* ob = o + (size_t)b * TT * CC + h * DD;

    float rqk = (tid < 64) ? qb[tid] : kb[tid - 64];
    float rv = vb[d];
    float rb = bb[0];

    int buf = 0;
    for (int t = 0; t < TT; t++) {
        if (tid < 64) qs[buf][tid] = rqk; else ks[buf][tid - 64] = rqk;
        __syncthreads();
        float cv = rv, cb = rb;
        if (t + 1 < TT) {
            const int off = (t + 1) * CC;
            rqk = (tid < 64) ? qb[off + tid] : kb[off + tid - 64];
            rv = vb[off + d];
            rb = bb[(t + 1) * HH];
        }
        float po0 = 0.f, po1 = 0.f, pm0 = 0.f, pm1 = 0.f;
#pragma unroll
        for (int j = 0; j < 32; j += 2) {
            float q0 = qs[buf][cbase + j], q1 = qs[buf][cbase + j + 1];
            float k0 = ks[buf][cbase + j], k1 = ks[buf][cbase + j + 1];
            po0 += Mrow[j] * q0;
            po1 += Mrow[j + 1] * q1;
            pm0 += Mrow[j] * k0;
            pm1 += Mrow[j + 1] * k1;
        }
        float po = po0 + po1, pm = pm0 + pm1;
        po += __shfl_xor_sync(0xffffffffu, po, 1);
        pm += __shfl_xor_sync(0xffffffffu, pm, 1);
        float dvb = cb * (cv - pm);
#pragma unroll
        for (int j = 0; j < 32; j++) Mrow[j] += dvb * ks[buf][cbase + j];
        if (s == 0) ob[(size_t)t * CC + d] = po;
        buf ^= 1;
    }
}

// ---------------- launch ------------------------------------------------------
extern "C" void kernel_launch(void* const* d_in, const int* in_sizes, int n_in,
                              void* d_out, int out_size) {
    const float* x       = (const float*)d_in[0];
    const float* norm1_w = (const float*)d_in[3];
    const float* norm2_w = (const float*)d_in[4];
    const float* q_w     = (const float*)d_in[5];
    const float* k_w     = (const float*)d_in[6];
    const float* v_w     = (const float*)d_in[7];
    const float* beta_w  = (const float*)d_in[8];
    const float* beta_b  = (const float*)d_in[9];
    const float* gate_w  = (const float*)d_in[10];
    const float* o_w     = (const float*)d_in[11];
    const float* fg_w    = (const float*)d_in[12];
    const float* fu_w    = (const float*)d_in[13];
    const float* fd_w    = (const float*)d_in[14];
    float* out = (float*)d_out;

    float *xn, *q, *k, *v, *gate, *o, *x1, *beta, *gg, *uu;
    __nv_bfloat16 *ah, *al, *wh, *wl;
    cudaGetSymbolAddress((void**)&xn,   g_xn);
    cudaGetSymbolAddress((void**)&q,    g_q);
    cudaGetSymbolAddress((void**)&k,    g_k);
    cudaGetSymbolAddress((void**)&v,    g_v);
    cudaGetSymbolAddress((void**)&gate, g_gate);
    cudaGetSymbolAddress((void**)&o,    g_o);
    cudaGetSymbolAddress((void**)&x1,   g_x1);
    cudaGetSymbolAddress((void**)&beta, g_beta);
    cudaGetSymbolAddress((void**)&gg,   g_gg);
    cudaGetSymbolAddress((void**)&uu,   g_uu);
    cudaGetSymbolAddress((void**)&ah,   g_a_hi);
    cudaGetSymbolAddress((void**)&al,   g_a_lo);
    cudaGetSymbolAddress((void**)&wh,   g_w_hi);
    cudaGetSymbolAddress((void**)&wl,   g_w_lo);

    cudaFuncSetAttribute(gemm_mma, cudaFuncAttributeMaxDynamicSharedMemorySize,
                         GSMEM_TOTAL);

    const int EW = MROWS * CC / 256;

    auto cvt = [&](const float* src, __nv_bfloat16* h, __nv_bfloat16* l, int n) {
        cvt_split_k<<<(n / 4 + 255) / 256, 256>>>(src, h, l, n / 4);
    };
    auto gemm = [&](float* Cm, int N, int K) {
        gemm_mma<<<dim3(N / TILE_MN, MROWS / TILE_MN), 256, GSMEM_TOTAL>>>(
            Cm, ah, al, wh, wl, MROWS, N, K);
    };

    // ---- attention branch ----
    rmsnorm_k<<<MROWS, 256>>>(x, norm1_w, xn);
    cvt(xn, ah, al, MROWS * CC);
    cvt(q_w, wh, wl, CC * CC);    gemm(q,    CC, CC);
    cvt(k_w, wh, wl, CC * CC);    gemm(k,    CC, CC);
    cvt(v_w, wh, wl, CC * CC);    gemm(v,    CC, CC);
    cvt(gate_w, wh, wl, CC * CC); gemm(gate, CC, CC);
    sgemm_nt<<<dim3(1, MROWS / 128), 256>>>(xn, beta_w, beta, MROWS, HH, CC);
    beta_post_k<<<(MROWS * HH) / 256, 256>>>(beta, beta_b);
    l2norm_k<<<(MROWS * HH) / 8, 256>>>(q);
    l2norm_k<<<(MROWS * HH) / 8, 256>>>(k);
    delta_scan_k<<<BB * HH, 128>>>(q, k, v, beta, o);
    gate_mul_k<<<EW, 256>>>(gate, o);
    cvt(gate, ah, al, MROWS * CC);
    cvt(o_w, wh, wl, CC * CC);    gemm(v, CC, CC);   // v <- attn out
    resadd_k<<<EW, 256>>>(x, v, x1);

    // ---- FFN branch ----
    rmsnorm_k<<<MROWS, 256>>>(x1, norm2_w, xn);
    cvt(xn, ah, al, MROWS * CC);
    cvt(fg_w, wh, wl, FF * CC);   gemm(gg, FF, CC);
    cvt(fu_w, wh, wl, FF * CC);   gemm(uu, FF, CC);
    silu_mul_k<<<(MROWS * FF) / 256, 256>>>(gg, uu);
    cvt(gg, ah, al, MROWS * FF);
    cvt(fd_w, wh, wl, CC * FF);   gemm(out, CC, FF);
    final_add_k<<<EW, 256>>>(out, x1);
}

// round 5
// speedup vs baseline: 2.5815x; 1.0271x over previous
#include <cuda_runtime.h>
#include <cuda_bf16.h>
#include <cstdint>
#include <math.h>

#define BB 4
#define TT 2048
#define CC 1024
#define HH 16
#define DD 64
#define FF 4096
#define MROWS (BB*TT)   // 8192

// ---------------- scratch (static device globals; no allocation) -------------
__device__ float g_xn[MROWS*CC];
__device__ float g_q[MROWS*CC];
__device__ float g_k[MROWS*CC];
__device__ float g_v[MROWS*CC];     // reused as attn-proj output
__device__ float g_gate[MROWS*CC];
__device__ float g_o[MROWS*CC];
__device__ float g_x1[MROWS*CC];
__device__ float g_beta[MROWS*HH];
__device__ float g_gg[MROWS*FF];
__device__ float g_uu[MROWS*FF];
// bf16 split buffers
__device__ __align__(16) __nv_bfloat16 g_a_hi[MROWS*FF];
__device__ __align__(16) __nv_bfloat16 g_a_lo[MROWS*FF];
__device__ __align__(16) __nv_bfloat16 g_w_hi[FF*CC];
__device__ __align__(16) __nv_bfloat16 g_w_lo[FF*CC];

// ================= PTX helpers (plain sm_103-safe: sm_80-era ops only) =======
__device__ __forceinline__ uint32_t smem_u32(const void* p) {
    return (uint32_t)__cvta_generic_to_shared(p);
}
__device__ __forceinline__ void cp16(uint32_t dst, const void* src) {
    asm volatile("cp.async.cg.shared.global [%0], [%1], 16;\n" :: "r"(dst), "l"(src));
}
__device__ __forceinline__ void cp_commit() {
    asm volatile("cp.async.commit_group;\n" ::: "memory");
}
__device__ __forceinline__ void ldsm4(uint32_t* d, uint32_t addr) {
    asm volatile("ldmatrix.sync.aligned.m8n8.x4.shared.b16 {%0,%1,%2,%3}, [%4];"
                 : "=r"(d[0]), "=r"(d[1]), "=r"(d[2]), "=r"(d[3]) : "r"(addr));
}
__device__ __forceinline__ void mma_bf16(float* c, const uint32_t* a,
                                         uint32_t b0, uint32_t b1) {
    asm volatile(
        "mma.sync.aligned.m16n8k16.row.col.f32.bf16.bf16.f32 "
        "{%0,%1,%2,%3}, {%4,%5,%6,%7}, {%8,%9}, {%0,%1,%2,%3};"
        : "+f"(c[0]), "+f"(c[1]), "+f"(c[2]), "+f"(c[3])
        : "r"(a[0]), "r"(a[1]), "r"(a[2]), "r"(a[3]), "r"(b0), "r"(b1));
}

// ================= split-bf16 GEMM via mma.sync ==============================
// C[M,N] = (Ah+Al)[M,K] * (Bh+Bl)[N,K]^T (fp32), via hh + hl + lh.
// CTA 128x128, 8 warps (warp tile 32x64), K staged 64, SW128 swizzle, 2 stages.
#define TILE_MN 128
#define KT 64
#define SUB_BYTES (128*128)         // one 128-row x 128B subtile = 16KB
#define OFF_A_HI 0
#define OFF_A_LO (SUB_BYTES)
#define OFF_B_HI (2*SUB_BYTES)
#define OFF_B_LO (3*SUB_BYTES)
#define STAGE_BYTES (4*SUB_BYTES)   // 64KB
#define GSMEM_TOTAL (2*STAGE_BYTES) // 128KB

__device__ __forceinline__ void load_tile(const __nv_bfloat16* __restrict__ g, int ldk,
                                          int row0, int k0, uint32_t dstbase, int tid) {
    // 128 rows x 128B (64 bf16), SW128 swizzle
#pragma unroll
    for (int i = tid; i < 128 * 8; i += 256) {
        int r = i >> 3;
        int c16 = i & 7;
        const __nv_bfloat16* src = g + (size_t)(row0 + r) * ldk + k0 + c16 * 8;
        uint32_t dst = dstbase + r * 128 + (((uint32_t)(c16 ^ (r & 7))) << 4);
        cp16(dst, src);
    }
}

__global__ __launch_bounds__(256, 1)
void gemm_mma(float* __restrict__ C,
              const __nv_bfloat16* __restrict__ Ah, const __nv_bfloat16* __restrict__ Al,
              const __nv_bfloat16* __restrict__ Bh, const __nv_bfloat16* __restrict__ Bl,
              int M, int N, int K) {
    extern __shared__ __align__(1024) char smem[];
    const uint32_t sbase = smem_u32(smem);
    const int tid = threadIdx.x;
    const int wid = tid >> 5;
    const int lane = tid & 31;
    const int wm = wid & 3;          // 4 m-groups of 32 rows
    const int wn = wid >> 2;         // 2 n-groups of 64 cols
    const int bm = blockIdx.y * TILE_MN;
    const int bn = blockIdx.x * TILE_MN;

    // ldmatrix per-lane addressing constants
    const int mi = lane >> 3;        // matrix index 0..3
    const int lr = lane & 7;         // row within matrix
    // A: matrices {m0-7 k0, m8-15 k0, m0-7 k8, m8-15 k8}
    const uint32_t a_off = (uint32_t)(wm * 32 + ((mi & 1) << 3) + lr) * 128;
    const uint32_t a_cb = (uint32_t)(mi >> 1);
    // B: matrices {n0-7 k0, n0-7 k8, n8-15 k0, n8-15 k8}
    const uint32_t b_off = (uint32_t)(wn * 64 + ((mi >> 1) << 3) + lr) * 128;
    const uint32_t b_cb = (uint32_t)(mi & 1);

    float acc[2][8][4];
#pragma unroll
    for (int a = 0; a < 2; a++)
#pragma unroll
        for (int b = 0; b < 8; b++)
#pragma unroll
            for (int c = 0; c < 4; c++) acc[a][b][c] = 0.f;

    const int NC = K / KT;

    // prefetch chunks 0 and 1
    load_tile(Ah, K, bm, 0, sbase + OFF_A_HI, tid);
    load_tile(Al, K, bm, 0, sbase + OFF_A_LO, tid);
    load_tile(Bh, K, bn, 0, sbase + OFF_B_HI, tid);
    load_tile(Bl, K, bn, 0, sbase + OFF_B_LO, tid);
    cp_commit();
    load_tile(Ah, K, bm, KT, sbase + STAGE_BYTES + OFF_A_HI, tid);
    load_tile(Al, K, bm, KT, sbase + STAGE_BYTES + OFF_A_LO, tid);
    load_tile(Bh, K, bn, KT, sbase + STAGE_BYTES + OFF_B_HI, tid);
    load_tile(Bl, K, bn, KT, sbase + STAGE_BYTES + OFF_B_LO, tid);
    cp_commit();

    for (int kc = 0; kc < NC; kc++) {
        const uint32_t sb = sbase + (uint32_t)(kc & 1) * STAGE_BYTES;
        if (kc + 2 < NC) {
            asm volatile("cp.async.wait_group 1;\n" ::: "memory");
        } else {
            asm volatile("cp.async.wait_group 0;\n" ::: "memory");
        }
        __syncthreads();

#pragma unroll
        for (int ki = 0; ki < 4; ki++) {
            uint32_t ah[2][4], al[2][4], bh[4][4], bl[4][4];
            const uint32_t ax = ((uint32_t)(ki * 2) + a_cb) ^ (uint32_t)lr;
            const uint32_t bx = ((uint32_t)(ki * 2) + b_cb) ^ (uint32_t)lr;
#pragma unroll
            for (int mt = 0; mt < 2; mt++) {
                uint32_t aaddr = sb + a_off + (uint32_t)(mt * 2048) + (ax << 4);
                ldsm4(ah[mt], aaddr + OFF_A_HI);
                ldsm4(al[mt], aaddr + OFF_A_LO);
            }
#pragma unroll
            for (int nt = 0; nt < 4; nt++) {
                uint32_t baddr = sb + b_off + (uint32_t)(nt * 2048) + (bx << 4);
                ldsm4(bh[nt], baddr + OFF_B_HI);
                ldsm4(bl[nt], baddr + OFF_B_LO);
            }
            // 3 separated passes: within a pass all 16 accumulators are
            // independent, so dependent MMAs on the same accumulator are
            // >= 16 issue slots apart (hides HMMA latency).
#pragma unroll
            for (int sp = 0; sp < 3; sp++) {
#pragma unroll
                for (int mt = 0; mt < 2; mt++)
#pragma unroll
                    for (int nt = 0; nt < 4; nt++)
#pragma unroll
                        for (int h = 0; h < 2; h++) {
                            const uint32_t* a = (sp == 2) ? al[mt] : ah[mt];
                            const uint32_t* b = (sp == 1) ? bl[nt] : bh[nt];
                            mma_bf16(acc[mt][nt * 2 + h], a, b[2 * h], b[2 * h + 1]);
                        }
            }
        }
        __syncthreads();
        if (kc + 2 < NC) {
            const uint32_t pb = sbase + (uint32_t)(kc & 1) * STAGE_BYTES;
            const int k0 = (kc + 2) * KT;
            load_tile(Ah, K, bm, k0, pb + OFF_A_HI, tid);
            load_tile(Al, K, bm, k0, pb + OFF_A_LO, tid);
            load_tile(Bh, K, bn, k0, pb + OFF_B_HI, tid);
            load_tile(Bl, K, bn, k0, pb + OFF_B_LO, tid);
            cp_commit();
        }
    }

    // epilogue: lane g = lane>>2 (row), t = lane&3 (col pair)
    const int g = lane >> 2;
    const int t = lane & 3;
#pragma unroll
    for (int mt = 0; mt < 2; mt++) {
        const int row0 = bm + wm * 32 + mt * 16 + g;
#pragma unroll
        for (int n8 = 0; n8 < 8; n8++) {
            const int col = bn + wn * 64 + n8 * 8 + t * 2;
            float* c = acc[mt][n8];
            *(float2*)(C + (size_t)row0 * N + col)       = make_float2(c[0], c[1]);
            *(float2*)(C + (size_t)(row0 + 8) * N + col) = make_float2(c[2], c[3]);
        }
    }
}

// ---------------- split helpers ----------------------------------------------
__device__ __forceinline__ void split_store(__nv_bfloat16* hi, __nv_bfloat16* lo,
                                            int i4, float4 v) {
    __nv_bfloat16 h0 = __float2bfloat16(v.x);
    __nv_bfloat16 h1 = __float2bfloat16(v.y);
    __nv_bfloat16 h2 = __float2bfloat16(v.z);
    __nv_bfloat16 h3 = __float2bfloat16(v.w);
    __nv_bfloat16 l0 = __float2bfloat16(v.x - __bfloat162float(h0));
    __nv_bfloat16 l1 = __float2bfloat16(v.y - __bfloat162float(h1));
    __nv_bfloat16 l2 = __float2bfloat16(v.z - __bfloat162float(h2));
    __nv_bfloat16 l3 = __float2bfloat16(v.w - __bfloat162float(h3));
    ((__nv_bfloat162*)hi)[2 * i4]     = __nv_bfloat162(h0, h1);
    ((__nv_bfloat162*)hi)[2 * i4 + 1] = __nv_bfloat162(h2, h3);
    ((__nv_bfloat162*)lo)[2 * i4]     = __nv_bfloat162(l0, l1);
    ((__nv_bfloat162*)lo)[2 * i4 + 1] = __nv_bfloat162(l2, l3);
}

// fp32 -> (hi, lo) bf16 split conversion (weights)
__global__ void cvt_split_k(const float* __restrict__ x, __nv_bfloat16* __restrict__ hi,
                            __nv_bfloat16* __restrict__ lo, int n4) {
    int i = blockIdx.x * 256 + threadIdx.x;
    if (i >= n4) return;
    split_store(hi, lo, i, ((const float4*)x)[i]);
}

// ---------------- rmsnorm (fused split output) --------------------------------
__global__ void rmsnorm_split_k(const float* __restrict__ x, const float* __restrict__ w,
                                float* __restrict__ y, __nv_bfloat16* __restrict__ hi,
                                __nv_bfloat16* __restrict__ lo) {
    int row = blockIdx.x;
    const float* xr = x + (size_t)row * CC;
    float* yr = y + (size_t)row * CC;
    float v[4];
    float ss = 0.f;
#pragma unroll
    for (int i = 0; i < 4; i++) {
        v[i] = xr[threadIdx.x + i * 256];
        ss += v[i] * v[i];
    }
#pragma unroll
    for (int off = 16; off; off >>= 1) ss += __shfl_xor_sync(0xffffffffu, ss, off);
    __shared__ float sred[8];
    __shared__ float stot;
    if ((threadIdx.x & 31) == 0) sred[threadIdx.x >> 5] = ss;
    __syncthreads();
    if (threadIdx.x < 8) {
        float t = sred[threadIdx.x];
#pragma unroll
        for (int off = 4; off; off >>= 1) t += __shfl_xor_sync(0xffu, t, off);
        if (threadIdx.x == 0) stot = t;
    }
    __syncthreads();
    float r = rsqrtf(stot / (float)CC + 1e-6f);
    float out[4];
#pragma unroll
    for (int i = 0; i < 4; i++) {
        out[i] = v[i] * r * w[threadIdx.x + i * 256];
        yr[threadIdx.x + i * 256] = out[i];
    }
    // split-store 4 consecutive? our layout above is strided; redo contiguous:
    // use a second pass: each thread handles one float4 of the row.
    const float4* y4 = (const float4*)yr;
    __syncthreads();
    float4 vv = y4[threadIdx.x];
    split_store(hi + (size_t)row * CC, lo + (size_t)row * CC, threadIdx.x, vv);
}

// ---------------- small FFMA GEMM (beta only, N=16) --------------------------
__global__ __launch_bounds__(256)
void sgemm_nt(const float* __restrict__ A, const float* __restrict__ B,
              float* __restrict__ C, int M, int N, int K) {
    __shared__ float As[8][128];
    __shared__ float Bs[8][128];
    const int tid = threadIdx.x;
    const int bm = blockIdx.y * 128;
    const int bn = blockIdx.x * 128;
    const int lrow = tid >> 1;
    const int lcol = (tid & 1) << 2;
    const int tx = tid & 15;
    const int ty = tid >> 4;

    const float* Aptr = A + (size_t)(bm + lrow) * K + lcol;
    const float* Bptr = B + (size_t)(bn + lrow) * K + lcol;
    const bool bvalid = (bn + lrow) < N;

    float acc[8][8];
#pragma unroll
    for (int i = 0; i < 8; i++)
#pragma unroll
        for (int j = 0; j < 8; j++) acc[i][j] = 0.f;

    for (int k0 = 0; k0 < K; k0 += 8) {
        float4 av = *(const float4*)(Aptr + k0);
        float4 bv = bvalid ? *(const float4*)(Bptr + k0) : make_float4(0.f, 0.f, 0.f, 0.f);
        As[lcol + 0][lrow] = av.x; As[lcol + 1][lrow] = av.y;
        As[lcol + 2][lrow] = av.z; As[lcol + 3][lrow] = av.w;
        Bs[lcol + 0][lrow] = bv.x; Bs[lcol + 1][lrow] = bv.y;
        Bs[lcol + 2][lrow] = bv.z; Bs[lcol + 3][lrow] = bv.w;
        __syncthreads();
#pragma unroll
        for (int kk = 0; kk < 8; kk++) {
            float ar[8], br[8];
            *(float4*)(ar)     = *(const float4*)&As[kk][ty * 8];
            *(float4*)(ar + 4) = *(const float4*)&As[kk][ty * 8 + 4];
            *(float4*)(br)     = *(const float4*)&Bs[kk][tx * 8];
            *(float4*)(br + 4) = *(const float4*)&Bs[kk][tx * 8 + 4];
#pragma unroll
            for (int i = 0; i < 8; i++)
#pragma unroll
                for (int j = 0; j < 8; j++)
                    acc[i][j] += ar[i] * br[j];
        }
        __syncthreads();
    }
#pragma unroll
    for (int i = 0; i < 8; i++) {
        int row = bm + ty * 8 + i;
#pragma unroll
        for (int j = 0; j < 8; j++) {
            int col = bn + tx * 8 + j;
            if (col < N) C[(size_t)row * N + col] = acc[i][j];
        }
    }
}

// ---------------- elementwise helpers ----------------------------------------
__global__ void beta_post_k(float* __restrict__ b, const float* __restrict__ bias) {
    int i = blockIdx.x * 256 + threadIdx.x;
    if (i < MROWS * HH) {
        float t = b[i] + bias[i & (HH - 1)];
        b[i] = 1.f / (1.f + __expf(-t));
    }
}

__global__ void l2norm_k(float* __restrict__ x) {
    int vec = blockIdx.x * 8 + (threadIdx.x >> 5);
    int lane = threadIdx.x & 31;
    float* p = x + (size_t)vec * 64;
    float a = p[lane], b = p[lane + 32];
    float ss = a * a + b * b;
#pragma unroll
    for (int off = 16; off; off >>= 1) ss += __shfl_xor_sync(0xffffffffu, ss, off);
    float inv = 1.f / fmaxf(sqrtf(ss), 1e-12f);
    p[lane] = a * inv;
    p[lane + 32] = b * inv;
}

// sigmoid(gate)*o -> split bf16
__global__ void gate_mul_split_k(const float* __restrict__ gate, const float* __restrict__ o,
                                 __nv_bfloat16* __restrict__ hi, __nv_bfloat16* __restrict__ lo) {
    int i = blockIdx.x * 256 + threadIdx.x;
    float4 gv = ((const float4*)gate)[i];
    float4 ov = ((const float4*)o)[i];
    float4 r;
    r.x = ov.x / (1.f + __expf(-gv.x));
    r.y = ov.y / (1.f + __expf(-gv.y));
    r.z = ov.z / (1.f + __expf(-gv.z));
    r.w = ov.w / (1.f + __expf(-gv.w));
    split_store(hi, lo, i, r);
}

__global__ void resadd_k(const float* __restrict__ a, const float* __restrict__ b,
                         float* __restrict__ y) {
    int i = blockIdx.x * 256 + threadIdx.x;
    y[i] = a[i] + b[i];
}

// silu(g)*u -> split bf16
__global__ void silu_mul_split_k(const float* __restrict__ g, const float* __restrict__ u,
                                 __nv_bfloat16* __restrict__ hi, __nv_bfloat16* __restrict__ lo) {
    int i = blockIdx.x * 256 + threadIdx.x;
    float4 gv = ((const float4*)g)[i];
    float4 uv = ((const float4*)u)[i];
    float4 r;
    r.x = (gv.x / (1.f + __expf(-gv.x))) * uv.x;
    r.y = (gv.y / (1.f + __expf(-gv.y))) * uv.y;
    r.z = (gv.z / (1.f + __expf(-gv.z))) * uv.z;
    r.w = (gv.w / (1.f + __expf(-gv.w))) * uv.w;
    split_store(hi, lo, i, r);
}

__global__ void final_add_k(float* __restrict__ out, const float* __restrict__ x1) {
    int i = blockIdx.x * 256 + threadIdx.x;
    out[i] += x1[i];
}

// ---------------- delta-rule scan --------------------------------------------
__global__ __launch_bounds__(128)
void delta_scan_k(const float* __restrict__ q, const float* __restrict__ k,
                  const float* __restrict__ v, const float* __restrict__ beta,
                  float* __restrict__ o) {
    const int b = blockIdx.x / HH;
    const int h = blockIdx.x % HH;
    const int tid = threadIdx.x;
    const int d = tid >> 1;
    const int s = tid & 1;
    const int cbase = s * 32;

    __shared__ float qs[2][64];
    __shared__ float ks[2][64];

    float Mrow[32];
#pragma unroll
    for (int j = 0; j < 32; j++) Mrow[j] = 0.f;

    const float* qb = q + (size_t)b * TT * CC + h * DD;
    const float* kb = k + (size_t)b * TT * CC + h * DD;
    const float* vb = v + (size_t)b * TT * CC + h * DD;
    const float* bb = beta + (size_t)b * TT * HH + h;
    float* ob = o + (size_t)b * TT * CC + h * DD;

    float rqk = (tid < 64) ? qb[tid] : kb[tid - 64];
    float rv = vb[d];
    float rb = bb[0];

    int buf = 0;
    for (int t = 0; t < TT; t++) {
        if (tid < 64) qs[buf][tid] = rqk; else ks[buf][tid - 64] = rqk;
        __syncthreads();
        float cv = rv, cb = rb;
        if (t + 1 < TT) {
            const int off = (t + 1) * CC;
            rqk = (tid < 64) ? qb[off + tid] : kb[off + tid - 64];
            rv = vb[off + d];
            rb = bb[(t + 1) * HH];
        }
        float po0 = 0.f, po1 = 0.f, pm0 = 0.f, pm1 = 0.f;
#pragma unroll
        for (int j = 0; j < 32; j += 2) {
            float q0 = qs[buf][cbase + j], q1 = qs[buf][cbase + j + 1];
            float k0 = ks[buf][cbase + j], k1 = ks[buf][cbase + j + 1];
            po0 += Mrow[j] * q0;
            po1 += Mrow[j + 1] * q1;
            pm0 += Mrow[j] * k0;
            pm1 += Mrow[j + 1] * k1;
        }
        float po = po0 + po1, pm = pm0 + pm1;
        po += __shfl_xor_sync(0xffffffffu, po, 1);
        pm += __shfl_xor_sync(0xffffffffu, pm, 1);
        float dvb = cb * (cv - pm);
#pragma unroll
        for (int j = 0; j < 32; j++) Mrow[j] += dvb * ks[buf][cbase + j];
        if (s == 0) ob[(size_t)t * CC + d] = po;
        buf ^= 1;
    }
}

// ---------------- launch ------------------------------------------------------
extern "C" void kernel_launch(void* const* d_in, const int* in_sizes, int n_in,
                              void* d_out, int out_size) {
    const float* x       = (const float*)d_in[0];
    const float* norm1_w = (const float*)d_in[3];
    const float* norm2_w = (const float*)d_in[4];
    const float* q_w     = (const float*)d_in[5];
    const float* k_w     = (const float*)d_in[6];
    const float* v_w     = (const float*)d_in[7];
    const float* beta_w  = (const float*)d_in[8];
    const float* beta_b  = (const float*)d_in[9];
    const float* gate_w  = (const float*)d_in[10];
    const float* o_w     = (const float*)d_in[11];
    const float* fg_w    = (const float*)d_in[12];
    const float* fu_w    = (const float*)d_in[13];
    const float* fd_w    = (const float*)d_in[14];
    float* out = (float*)d_out;

    float *xn, *q, *k, *v, *gate, *o, *x1, *beta, *gg, *uu;
    __nv_bfloat16 *ah, *al, *wh, *wl;
    cudaGetSymbolAddress((void**)&xn,   g_xn);
    cudaGetSymbolAddress((void**)&q,    g_q);
    cudaGetSymbolAddress((void**)&k,    g_k);
    cudaGetSymbolAddress((void**)&v,    g_v);
    cudaGetSymbolAddress((void**)&gate, g_gate);
    cudaGetSymbolAddress((void**)&o,    g_o);
    cudaGetSymbolAddress((void**)&x1,   g_x1);
    cudaGetSymbolAddress((void**)&beta, g_beta);
    cudaGetSymbolAddress((void**)&gg,   g_gg);
    cudaGetSymbolAddress((void**)&uu,   g_uu);
    cudaGetSymbolAddress((void**)&ah,   g_a_hi);
    cudaGetSymbolAddress((void**)&al,   g_a_lo);
    cudaGetSymbolAddress((void**)&wh,   g_w_hi);
    cudaGetSymbolAddress((void**)&wl,   g_w_lo);

    cudaFuncSetAttribute(gemm_mma, cudaFuncAttributeMaxDynamicSharedMemorySize,
                         GSMEM_TOTAL);

    const int EW = MROWS * CC / 256;
    const int EW4 = MROWS * CC / 4 / 256;

    auto cvt = [&](const float* src, __nv_bfloat16* h, __nv_bfloat16* l, int n) {
        cvt_split_k<<<(n / 4 + 255) / 256, 256>>>(src, h, l, n / 4);
    };
    auto gemm = [&](float* Cm, int N, int K) {
        gemm_mma<<<dim3(N / TILE_MN, MROWS / TILE_MN), 256, GSMEM_TOTAL>>>(
            Cm, ah, al, wh, wl, MROWS, N, K);
    };

    // ---- attention branch ----
    rmsnorm_split_k<<<MROWS, 256>>>(x, norm1_w, xn, ah, al);
    cvt(q_w, wh, wl, CC * CC);    gemm(q,    CC, CC);
    cvt(k_w, wh, wl, CC * CC);    gemm(k,    CC, CC);
    cvt(v_w, wh, wl, CC * CC);    gemm(v,    CC, CC);
    cvt(gate_w, wh, wl, CC * CC); gemm(gate, CC, CC);
    sgemm_nt<<<dim3(1, MROWS / 128), 256>>>(xn, beta_w, beta, MROWS, HH, CC);
    beta_post_k<<<(MROWS * HH) / 256, 256>>>(beta, beta_b);
    l2norm_k<<<(MROWS * HH) / 8, 256>>>(q);
    l2norm_k<<<(MROWS * HH) / 8, 256>>>(k);
    delta_scan_k<<<BB * HH, 128>>>(q, k, v, beta, o);
    gate_mul_split_k<<<EW4, 256>>>(gate, o, ah, al);
    cvt(o_w, wh, wl, CC * CC);    gemm(v, CC, CC);   // v <- attn out
    resadd_k<<<EW, 256>>>(x, v, x1);

    // ---- FFN branch ----
    rmsnorm_split_k<<<MROWS, 256>>>(x1, norm2_w, xn, ah, al);
    cvt(fg_w, wh, wl, FF * CC);   gemm(gg, FF, CC);
    cvt(fu_w, wh, wl, FF * CC);   gemm(uu, FF, CC);
    silu_mul_split_k<<<MROWS * FF / 4 / 256, 256>>>(gg, uu, ah, al);
    cvt(fd_w, wh, wl, CC * FF);   gemm(out, CC, FF);
    final_add_k<<<EW, 256>>>(out, x1);
}